// round 1
// baseline (speedup 1.0000x reference)
#include <cuda_runtime.h>
#include <cuda_bf16.h>
#include <math.h>

// Problem shape (fixed)
#define BB 8
#define LL 2048
#define DD 1024
#define NH 16
#define HD 64
#define MTOK (BB * LL)        // 16384 tokens

// ---------------- scratch (static device globals; no allocation) -----------
__device__ float g_Q[(size_t)MTOK * DD];
__device__ float g_K[(size_t)MTOK * DD];
__device__ float g_V[(size_t)MTOK * DD];
__device__ float g_Y[(size_t)MTOK * DD];

// ---------------- GEMM: C[M,N] = A[M,K] @ B[K,N] + bias[N] -----------------
// 128x128 tile, BK=16, 256 threads, 8x8 per-thread microtile, float4 I/O.
#define BM 128
#define BN 128
#define BK 16
#define TM 8
#define TN 8

__global__ void __launch_bounds__(256) gemm_bias_kernel(
    const float* __restrict__ A, const float* __restrict__ B,
    const float* __restrict__ bias, float* __restrict__ C,
    int M, int N, int K)
{
    __shared__ float As[BK][BM + 4];   // transposed A tile, padded
    __shared__ float Bs[BK][BN];

    const int tid = threadIdx.x;
    const int tx = tid & 15;           // 0..15 (N direction)
    const int ty = tid >> 4;           // 0..15 (M direction)
    const int block_m = blockIdx.y * BM;
    const int block_n = blockIdx.x * BN;

    // A load mapping: 2 x float4 per thread
    const int a_row = tid >> 2;        // 0..63
    const int a_col = (tid & 3) * 4;   // 0,4,8,12
    // B load mapping: 2 x float4 per thread
    const int b_row = tid >> 5;        // 0..7
    const int b_col = (tid & 31) * 4;  // 0..124

    float acc[TM][TN];
#pragma unroll
    for (int i = 0; i < TM; i++)
#pragma unroll
        for (int j = 0; j < TN; j++) acc[i][j] = 0.f;

    for (int kt = 0; kt < K; kt += BK) {
#pragma unroll
        for (int h = 0; h < 2; h++) {
            int r = a_row + h * 64;
            float4 v = *reinterpret_cast<const float4*>(
                &A[(size_t)(block_m + r) * K + kt + a_col]);
            As[a_col + 0][r] = v.x;
            As[a_col + 1][r] = v.y;
            As[a_col + 2][r] = v.z;
            As[a_col + 3][r] = v.w;
        }
#pragma unroll
        for (int h = 0; h < 2; h++) {
            int r = b_row + h * 8;
            *reinterpret_cast<float4*>(&Bs[r][b_col]) =
                *reinterpret_cast<const float4*>(
                    &B[(size_t)(kt + r) * N + block_n + b_col]);
        }
        __syncthreads();

#pragma unroll
        for (int k = 0; k < BK; k++) {
            float ra[TM], rb[TN];
            float4 a0 = *reinterpret_cast<const float4*>(&As[k][ty * TM + 0]);
            float4 a1 = *reinterpret_cast<const float4*>(&As[k][ty * TM + 4]);
            ra[0] = a0.x; ra[1] = a0.y; ra[2] = a0.z; ra[3] = a0.w;
            ra[4] = a1.x; ra[5] = a1.y; ra[6] = a1.z; ra[7] = a1.w;
            float4 b0 = *reinterpret_cast<const float4*>(&Bs[k][tx * TN + 0]);
            float4 b1 = *reinterpret_cast<const float4*>(&Bs[k][tx * TN + 4]);
            rb[0] = b0.x; rb[1] = b0.y; rb[2] = b0.z; rb[3] = b0.w;
            rb[4] = b1.x; rb[5] = b1.y; rb[6] = b1.z; rb[7] = b1.w;
#pragma unroll
            for (int i = 0; i < TM; i++)
#pragma unroll
                for (int j = 0; j < TN; j++)
                    acc[i][j] = fmaf(ra[i], rb[j], acc[i][j]);
        }
        __syncthreads();
    }

    // epilogue with bias
#pragma unroll
    for (int i = 0; i < TM; i++) {
        int row = block_m + ty * TM + i;
#pragma unroll
        for (int j = 0; j < TN; j += 4) {
            int col = block_n + tx * TN + j;
            float4 v;
            v.x = acc[i][j + 0] + bias[col + 0];
            v.y = acc[i][j + 1] + bias[col + 1];
            v.z = acc[i][j + 2] + bias[col + 2];
            v.w = acc[i][j + 3] + bias[col + 3];
            *reinterpret_cast<float4*>(&C[(size_t)row * N + col]) = v;
        }
    }
}

// ---------------- per-token attention ---------------------------------------
// q,k,v reshaped (HD=64, NH=16): flat index d = i*16 + j.
// scores[i][k] = dot_j(q[i], k[k]) / 4 + 1e-6, causal over 64x64 with
// value-nonzero mask semantics (exact 0.0 in lower tri -> masked).
__global__ void __launch_bounds__(64) attn_kernel(
    const float* __restrict__ Q, const float* __restrict__ K,
    const float* __restrict__ V, float* __restrict__ Y)
{
    __shared__ float sq[HD * NH];
    __shared__ float sk[HD * NH];
    __shared__ float sv[HD * NH];

    const int t = blockIdx.x;
    const size_t base = (size_t)t * DD;
    const int tid = threadIdx.x;   // 0..63

    // stage the token's q/k/v rows (1024 floats each = 256 float4)
#pragma unroll
    for (int h = 0; h < 4; h++) {
        int idx = tid + h * 64;
        reinterpret_cast<float4*>(sq)[idx] =
            reinterpret_cast<const float4*>(Q + base)[idx];
        reinterpret_cast<float4*>(sk)[idx] =
            reinterpret_cast<const float4*>(K + base)[idx];
        reinterpret_cast<float4*>(sv)[idx] =
            reinterpret_cast<const float4*>(V + base)[idx];
    }
    __syncthreads();

    const int i = tid;  // my HD row
    float4 q0 = reinterpret_cast<const float4*>(sq)[i * 4 + 0];
    float4 q1 = reinterpret_cast<const float4*>(sq)[i * 4 + 1];
    float4 q2 = reinterpret_cast<const float4*>(sq)[i * 4 + 2];
    float4 q3 = reinterpret_cast<const float4*>(sq)[i * 4 + 3];

    float s[HD];
    float mx = -INFINITY;
#pragma unroll
    for (int kk = 0; kk < HD; kk++) {
        float4 k0 = reinterpret_cast<const float4*>(sk)[kk * 4 + 0];
        float4 k1 = reinterpret_cast<const float4*>(sk)[kk * 4 + 1];
        float4 k2 = reinterpret_cast<const float4*>(sk)[kk * 4 + 2];
        float4 k3 = reinterpret_cast<const float4*>(sk)[kk * 4 + 3];
        float dot = q0.x * k0.x + q0.y * k0.y + q0.z * k0.z + q0.w * k0.w
                  + q1.x * k1.x + q1.y * k1.y + q1.z * k1.z + q1.w * k1.w
                  + q2.x * k2.x + q2.y * k2.y + q2.z * k2.z + q2.w * k2.w
                  + q3.x * k3.x + q3.y * k3.y + q3.z * k3.z + q3.w * k3.w;
        float val = dot * 0.25f + 1e-6f;
        bool valid = (kk <= i) && (val != 0.0f);
        s[kk] = valid ? val : -INFINITY;
        if (valid) mx = fmaxf(mx, val);
    }

    float sum = 0.f;
#pragma unroll
    for (int kk = 0; kk < HD; kk++) {
        float e = (s[kk] == -INFINITY) ? 0.f : __expf(s[kk] - mx);
        s[kk] = e;
        sum += e;
    }
    float inv = 1.f / sum;

    float4 acc0 = {0, 0, 0, 0}, acc1 = {0, 0, 0, 0};
    float4 acc2 = {0, 0, 0, 0}, acc3 = {0, 0, 0, 0};
    for (int kk = 0; kk <= i; kk++) {
        float p = s[kk] * inv;
        float4 v0 = reinterpret_cast<const float4*>(sv)[kk * 4 + 0];
        float4 v1 = reinterpret_cast<const float4*>(sv)[kk * 4 + 1];
        float4 v2 = reinterpret_cast<const float4*>(sv)[kk * 4 + 2];
        float4 v3 = reinterpret_cast<const float4*>(sv)[kk * 4 + 3];
        acc0.x = fmaf(p, v0.x, acc0.x); acc0.y = fmaf(p, v0.y, acc0.y);
        acc0.z = fmaf(p, v0.z, acc0.z); acc0.w = fmaf(p, v0.w, acc0.w);
        acc1.x = fmaf(p, v1.x, acc1.x); acc1.y = fmaf(p, v1.y, acc1.y);
        acc1.z = fmaf(p, v1.z, acc1.z); acc1.w = fmaf(p, v1.w, acc1.w);
        acc2.x = fmaf(p, v2.x, acc2.x); acc2.y = fmaf(p, v2.y, acc2.y);
        acc2.z = fmaf(p, v2.z, acc2.z); acc2.w = fmaf(p, v2.w, acc2.w);
        acc3.x = fmaf(p, v3.x, acc3.x); acc3.y = fmaf(p, v3.y, acc3.y);
        acc3.z = fmaf(p, v3.z, acc3.z); acc3.w = fmaf(p, v3.w, acc3.w);
    }

    float4* out = reinterpret_cast<float4*>(Y + base + (size_t)i * NH);
    out[0] = acc0; out[1] = acc1; out[2] = acc2; out[3] = acc3;
}

// ---------------- launch ----------------------------------------------------
extern "C" void kernel_launch(void* const* d_in, const int* in_sizes, int n_in,
                              void* d_out, int out_size)
{
    const float* x  = (const float*)d_in[0];
    const float* Wq = (const float*)d_in[1];
    const float* bq = (const float*)d_in[2];
    const float* Wk = (const float*)d_in[3];
    const float* bk = (const float*)d_in[4];
    const float* Wv = (const float*)d_in[5];
    const float* bv = (const float*)d_in[6];
    const float* Wo = (const float*)d_in[7];
    const float* bo = (const float*)d_in[8];
    float* out = (float*)d_out;

    float *Qp, *Kp, *Vp, *Yp;
    cudaGetSymbolAddress((void**)&Qp, g_Q);
    cudaGetSymbolAddress((void**)&Kp, g_K);
    cudaGetSymbolAddress((void**)&Vp, g_V);
    cudaGetSymbolAddress((void**)&Yp, g_Y);

    dim3 grid(DD / BN, MTOK / BM);   // (8, 128)

    gemm_bias_kernel<<<grid, 256>>>(x, Wq, bq, Qp, MTOK, DD, DD);
    gemm_bias_kernel<<<grid, 256>>>(x, Wk, bk, Kp, MTOK, DD, DD);
    gemm_bias_kernel<<<grid, 256>>>(x, Wv, bv, Vp, MTOK, DD, DD);

    attn_kernel<<<MTOK, 64>>>(Qp, Kp, Vp, Yp);

    gemm_bias_kernel<<<grid, 256>>>(Yp, Wo, bo, out, MTOK, DD, DD);
}

// round 3
// speedup vs baseline: 1.9633x; 1.9633x over previous
#include <cuda_runtime.h>
#include <cuda_bf16.h>
#include <math.h>
#include <stdint.h>

// Problem shape (fixed)
#define BB 8
#define LL 2048
#define DD 1024
#define NH 16
#define HD 64
#define MTOK (BB * LL)        // 16384 tokens
#define KTOT (3 * DD)         // 3072: [hi | lo | hi] x [hi | hi | lo]

// ======================= scratch ============================================
__device__ float g_Q[(size_t)MTOK * DD];
__device__ float g_K[(size_t)MTOK * DD];
__device__ float g_V[(size_t)MTOK * DD];
__device__ float g_Y[(size_t)MTOK * DD];
__device__ __nv_bfloat16 g_Aexp[(size_t)MTOK * KTOT];
__device__ __nv_bfloat16 g_Wexp[4ULL * DD * KTOT];

// ======================= small helpers ======================================
__device__ __forceinline__ uint32_t smem_u32(const void* p) {
    uint32_t a;
    asm("{ .reg .u64 t; cvta.to.shared.u64 t, %1; cvt.u32.u64 %0, t; }"
        : "=r"(a) : "l"(p));
    return a;
}
__device__ __forceinline__ void cp_async16(uint32_t dst, const void* src) {
    asm volatile("cp.async.cg.shared.global [%0], [%1], 16;" :: "r"(dst), "l"(src));
}
#define CP_COMMIT() asm volatile("cp.async.commit_group;" ::: "memory")

__device__ __forceinline__ void ldsm_x4(uint32_t* r, uint32_t addr) {
    asm volatile("ldmatrix.sync.aligned.m8n8.x4.shared.b16 {%0,%1,%2,%3}, [%4];"
                 : "=r"(r[0]), "=r"(r[1]), "=r"(r[2]), "=r"(r[3]) : "r"(addr));
}
__device__ __forceinline__ void mma16816(float* c, const uint32_t* a,
                                         uint32_t b0, uint32_t b1) {
    asm volatile(
        "mma.sync.aligned.m16n8k16.row.col.f32.bf16.bf16.f32 "
        "{%0,%1,%2,%3}, {%4,%5,%6,%7}, {%8,%9}, {%0,%1,%2,%3};"
        : "+f"(c[0]), "+f"(c[1]), "+f"(c[2]), "+f"(c[3])
        : "r"(a[0]), "r"(a[1]), "r"(a[2]), "r"(a[3]), "r"(b0), "r"(b1));
}

// ======================= conversion kernels =================================
// x [M, DD] fp32 -> Aexp [M, KTOT] bf16: [hi(0:1024) | lo(1024:2048) | hi(2048:3072)]
__global__ void __launch_bounds__(256) convert_Aexp_kernel(
    const float* __restrict__ in, __nv_bfloat16* __restrict__ out)
{
    int i = blockIdx.x * blockDim.x + threadIdx.x;   // one per 4 floats
    if (i >= MTOK * DD / 4) return;
    int row = i >> 8;                // DD/4 = 256
    int col = (i & 255) * 4;
    float4 v = reinterpret_cast<const float4*>(in)[i];
    __nv_bfloat16 h0 = __float2bfloat16_rn(v.x);
    __nv_bfloat16 h1 = __float2bfloat16_rn(v.y);
    __nv_bfloat16 h2 = __float2bfloat16_rn(v.z);
    __nv_bfloat16 h3 = __float2bfloat16_rn(v.w);
    __nv_bfloat16 l0 = __float2bfloat16_rn(v.x - __bfloat162float(h0));
    __nv_bfloat16 l1 = __float2bfloat16_rn(v.y - __bfloat162float(h1));
    __nv_bfloat16 l2 = __float2bfloat16_rn(v.z - __bfloat162float(h2));
    __nv_bfloat16 l3 = __float2bfloat16_rn(v.w - __bfloat162float(h3));
    __nv_bfloat162 ph0 = __halves2bfloat162(h0, h1);
    __nv_bfloat162 ph1 = __halves2bfloat162(h2, h3);
    __nv_bfloat162 pl0 = __halves2bfloat162(l0, l1);
    __nv_bfloat162 pl1 = __halves2bfloat162(l2, l3);
    uint2 uh, ul;
    uh.x = *reinterpret_cast<uint32_t*>(&ph0);
    uh.y = *reinterpret_cast<uint32_t*>(&ph1);
    ul.x = *reinterpret_cast<uint32_t*>(&pl0);
    ul.y = *reinterpret_cast<uint32_t*>(&pl1);
    size_t base = (size_t)row * KTOT;
    *reinterpret_cast<uint2*>(out + base + col) = uh;
    *reinterpret_cast<uint2*>(out + base + DD + col) = ul;
    *reinterpret_cast<uint2*>(out + base + 2 * DD + col) = uh;
}

// W [K=DD, N=DD] fp32 -> Wexp [N, KTOT] bf16: [hi | hi | lo] along K (transposed)
__global__ void __launch_bounds__(256) convert_Wexp_kernel(
    const float* __restrict__ W, __nv_bfloat16* __restrict__ T)
{
    __shared__ float t[32][33];
    int bx = blockIdx.x * 32, by = blockIdx.y * 32;
    int tx = threadIdx.x, ty = threadIdx.y;
    for (int j = ty; j < 32; j += 8)
        t[j][tx] = W[(size_t)(by + j) * DD + bx + tx];
    __syncthreads();
    for (int j = ty; j < 32; j += 8) {
        float v = t[tx][j];                 // element (k=by+tx, n=bx+j)
        __nv_bfloat16 h = __float2bfloat16_rn(v);
        __nv_bfloat16 l = __float2bfloat16_rn(v - __bfloat162float(h));
        size_t o = (size_t)(bx + j) * KTOT + by + tx;
        T[o] = h; T[o + DD] = h; T[o + 2 * DD] = l;
    }
}

// ======================= mma.sync GEMM ======================================
// C[M,N] = A''[M,KTOT] @ B''[N,KTOT]^T + bias
#define GBM 128
#define GBN 128
#define GBK 32
#define GSTAGES 4
#define APAD 8
#define SROW (GBK + APAD)                 // 40 bf16 = 80 B row stride
#define STAGE_ELEMS (GBM * SROW)          // 5120 bf16 = 10240 B (A or B tile)
#define STAGE_BYTES (STAGE_ELEMS * 2)
#define GEMM_SMEM (2 * GSTAGES * STAGE_BYTES)   // 81920 B
#define GNIT (KTOT / GBK)                 // 96

__global__ void __launch_bounds__(256) gemm_mma_kernel(
    const __nv_bfloat16* __restrict__ A, const __nv_bfloat16* __restrict__ B,
    const float* __restrict__ bias, float* __restrict__ C, int N)
{
    extern __shared__ __nv_bfloat16 sm[];
    const uint32_t sa = smem_u32(sm);                       // A stages
    const uint32_t sb = sa + GSTAGES * STAGE_BYTES;         // B stages

    const int tid = threadIdx.x;
    const int lane = tid & 31;
    const int wid = tid >> 5;
    const int wm = wid & 3;          // 0..3 -> 32-row slice
    const int wn = wid >> 2;         // 0..1 -> 64-col slice
    const int bm = blockIdx.y * GBM;
    const int bn = blockIdx.x * GBN;

    float acc[2][8][4];
#pragma unroll
    for (int i = 0; i < 2; i++)
#pragma unroll
        for (int j = 0; j < 8; j++)
#pragma unroll
            for (int q = 0; q < 4; q++) acc[i][j][q] = 0.f;

    // stage loader: 512 16B chunks each for A and B, 2 per thread per tile
    auto load_stage = [&](int it, int s) {
        const int kt = it * GBK;
#pragma unroll
        for (int i = 0; i < 2; i++) {
            int c = tid + 256 * i;
            int r = c >> 2, ch = c & 3;
            uint32_t off = s * STAGE_BYTES + (r * SROW + ch * 8) * 2;
            cp_async16(sa + off, A + (size_t)(bm + r) * KTOT + kt + ch * 8);
            cp_async16(sb + off, B + (size_t)(bn + r) * KTOT + kt + ch * 8);
        }
        CP_COMMIT();
    };

    load_stage(0, 0);
    load_stage(1, 1);
    load_stage(2, 2);

    // precomputed ldmatrix lane offsets (element units)
    const int a_row = wm * 32 + (lane & 15);
    const int a_kof = ((lane >> 4) & 1) * 8;
    const int b_row = wn * 64 + ((lane >> 4) & 1) * 8 + (lane & 7);
    const int b_kof = ((lane >> 3) & 1) * 8;

    for (int it = 0; it < GNIT; it++) {
        const int s = it & 3;
        asm volatile("cp.async.wait_group 2;" ::: "memory");
        __syncthreads();

        if (it + 3 < GNIT) load_stage(it + 3, (it + 3) & 3);
        else CP_COMMIT();   // keep group accounting uniform

        const uint32_t abase = sa + s * STAGE_BYTES;
        const uint32_t bbase = sb + s * STAGE_BYTES;
#pragma unroll
        for (int ks = 0; ks < 2; ks++) {
            const int k0 = ks * 16;
            uint32_t af[2][4];
#pragma unroll
            for (int mi = 0; mi < 2; mi++) {
                uint32_t addr = abase + ((a_row + mi * 16) * SROW + k0 + a_kof) * 2;
                ldsm_x4(af[mi], addr);
            }
            uint32_t bf[4][4];
#pragma unroll
            for (int nj = 0; nj < 4; nj++) {
                uint32_t addr = bbase + ((b_row + nj * 16) * SROW + k0 + b_kof) * 2;
                ldsm_x4(bf[nj], addr);   // {n0:k0-7, n0:k8-15, n8:k0-7, n8:k8-15}
            }
#pragma unroll
            for (int mi = 0; mi < 2; mi++)
#pragma unroll
                for (int nj = 0; nj < 4; nj++) {
                    mma16816(acc[mi][2 * nj],     af[mi], bf[nj][0], bf[nj][1]);
                    mma16816(acc[mi][2 * nj + 1], af[mi], bf[nj][2], bf[nj][3]);
                }
        }
    }

    // epilogue
#pragma unroll
    for (int mi = 0; mi < 2; mi++) {
#pragma unroll
        for (int ni = 0; ni < 8; ni++) {
            int row = bm + wm * 32 + mi * 16 + (lane >> 2);
            int col = bn + wn * 64 + ni * 8 + (lane & 3) * 2;
            float b0 = __ldg(&bias[col]), b1 = __ldg(&bias[col + 1]);
            float2 v0 = {acc[mi][ni][0] + b0, acc[mi][ni][1] + b1};
            float2 v1 = {acc[mi][ni][2] + b0, acc[mi][ni][3] + b1};
            *reinterpret_cast<float2*>(&C[(size_t)row * N + col]) = v0;
            *reinterpret_cast<float2*>(&C[(size_t)(row + 8) * N + col]) = v1;
        }
    }
}

// ======================= per-token attention ================================
__global__ void __launch_bounds__(64) attn_kernel(
    const float* __restrict__ Q, const float* __restrict__ K,
    const float* __restrict__ V, float* __restrict__ Y)
{
    __shared__ float sq[HD * NH];
    __shared__ float sk[HD * NH];
    __shared__ float sv[HD * NH];

    const int t = blockIdx.x;
    const size_t base = (size_t)t * DD;
    const int tid = threadIdx.x;

#pragma unroll
    for (int h = 0; h < 4; h++) {
        int idx = tid + h * 64;
        reinterpret_cast<float4*>(sq)[idx] = reinterpret_cast<const float4*>(Q + base)[idx];
        reinterpret_cast<float4*>(sk)[idx] = reinterpret_cast<const float4*>(K + base)[idx];
        reinterpret_cast<float4*>(sv)[idx] = reinterpret_cast<const float4*>(V + base)[idx];
    }
    __syncthreads();

    const int i = tid;
    float4 q0 = reinterpret_cast<const float4*>(sq)[i * 4 + 0];
    float4 q1 = reinterpret_cast<const float4*>(sq)[i * 4 + 1];
    float4 q2 = reinterpret_cast<const float4*>(sq)[i * 4 + 2];
    float4 q3 = reinterpret_cast<const float4*>(sq)[i * 4 + 3];

    float s[HD];
    float mx = -INFINITY;
#pragma unroll
    for (int kk = 0; kk < HD; kk++) {
        float4 k0 = reinterpret_cast<const float4*>(sk)[kk * 4 + 0];
        float4 k1 = reinterpret_cast<const float4*>(sk)[kk * 4 + 1];
        float4 k2 = reinterpret_cast<const float4*>(sk)[kk * 4 + 2];
        float4 k3 = reinterpret_cast<const float4*>(sk)[kk * 4 + 3];
        float dot = q0.x * k0.x + q0.y * k0.y + q0.z * k0.z + q0.w * k0.w
                  + q1.x * k1.x + q1.y * k1.y + q1.z * k1.z + q1.w * k1.w
                  + q2.x * k2.x + q2.y * k2.y + q2.z * k2.z + q2.w * k2.w
                  + q3.x * k3.x + q3.y * k3.y + q3.z * k3.z + q3.w * k3.w;
        float val = dot * 0.25f + 1e-6f;
        bool valid = (kk <= i) && (val != 0.0f);
        s[kk] = valid ? val : -INFINITY;
        if (valid) mx = fmaxf(mx, val);
    }

    float sum = 0.f;
#pragma unroll
    for (int kk = 0; kk < HD; kk++) {
        float e = (s[kk] == -INFINITY) ? 0.f : __expf(s[kk] - mx);
        s[kk] = e;
        sum += e;
    }
    float inv = 1.f / sum;

    float4 acc0 = {0, 0, 0, 0}, acc1 = {0, 0, 0, 0};
    float4 acc2 = {0, 0, 0, 0}, acc3 = {0, 0, 0, 0};
    for (int kk = 0; kk <= i; kk++) {
        float p = s[kk] * inv;
        float4 v0 = reinterpret_cast<const float4*>(sv)[kk * 4 + 0];
        float4 v1 = reinterpret_cast<const float4*>(sv)[kk * 4 + 1];
        float4 v2 = reinterpret_cast<const float4*>(sv)[kk * 4 + 2];
        float4 v3 = reinterpret_cast<const float4*>(sv)[kk * 4 + 3];
        acc0.x = fmaf(p, v0.x, acc0.x); acc0.y = fmaf(p, v0.y, acc0.y);
        acc0.z = fmaf(p, v0.z, acc0.z); acc0.w = fmaf(p, v0.w, acc0.w);
        acc1.x = fmaf(p, v1.x, acc1.x); acc1.y = fmaf(p, v1.y, acc1.y);
        acc1.z = fmaf(p, v1.z, acc1.z); acc1.w = fmaf(p, v1.w, acc1.w);
        acc2.x = fmaf(p, v2.x, acc2.x); acc2.y = fmaf(p, v2.y, acc2.y);
        acc2.z = fmaf(p, v2.z, acc2.z); acc2.w = fmaf(p, v2.w, acc2.w);
        acc3.x = fmaf(p, v3.x, acc3.x); acc3.y = fmaf(p, v3.y, acc3.y);
        acc3.z = fmaf(p, v3.z, acc3.z); acc3.w = fmaf(p, v3.w, acc3.w);
    }

    float4* out = reinterpret_cast<float4*>(Y + base + (size_t)i * NH);
    out[0] = acc0; out[1] = acc1; out[2] = acc2; out[3] = acc3;
}

// ======================= launch =============================================
extern "C" void kernel_launch(void* const* d_in, const int* in_sizes, int n_in,
                              void* d_out, int out_size)
{
    const float* x  = (const float*)d_in[0];
    const float* Wq = (const float*)d_in[1];
    const float* bq = (const float*)d_in[2];
    const float* Wk = (const float*)d_in[3];
    const float* bk = (const float*)d_in[4];
    const float* Wv = (const float*)d_in[5];
    const float* bv = (const float*)d_in[6];
    const float* Wo = (const float*)d_in[7];
    const float* bo = (const float*)d_in[8];
    float* out = (float*)d_out;

    float *Qp, *Kp, *Vp, *Yp;
    __nv_bfloat16 *Aexp, *Wexp;
    cudaGetSymbolAddress((void**)&Qp, g_Q);
    cudaGetSymbolAddress((void**)&Kp, g_K);
    cudaGetSymbolAddress((void**)&Vp, g_V);
    cudaGetSymbolAddress((void**)&Yp, g_Y);
    cudaGetSymbolAddress((void**)&Aexp, g_Aexp);
    cudaGetSymbolAddress((void**)&Wexp, g_Wexp);

    cudaFuncSetAttribute(gemm_mma_kernel,
                         cudaFuncAttributeMaxDynamicSharedMemorySize, GEMM_SMEM);

    const int n4 = MTOK * DD / 4;
    dim3 cgrid((n4 + 255) / 256);
    dim3 wgrid(DD / 32, DD / 32), wblk(32, 8);
    dim3 ggrid(DD / GBN, MTOK / GBM);    // (8, 128)

    convert_Aexp_kernel<<<cgrid, 256>>>(x, Aexp);
    convert_Wexp_kernel<<<wgrid, wblk>>>(Wq, Wexp + 0ULL * DD * KTOT);
    convert_Wexp_kernel<<<wgrid, wblk>>>(Wk, Wexp + 1ULL * DD * KTOT);
    convert_Wexp_kernel<<<wgrid, wblk>>>(Wv, Wexp + 2ULL * DD * KTOT);
    convert_Wexp_kernel<<<wgrid, wblk>>>(Wo, Wexp + 3ULL * DD * KTOT);

    gemm_mma_kernel<<<ggrid, 256, GEMM_SMEM>>>(Aexp, Wexp + 0ULL * DD * KTOT, bq, Qp, DD);
    gemm_mma_kernel<<<ggrid, 256, GEMM_SMEM>>>(Aexp, Wexp + 1ULL * DD * KTOT, bk, Kp, DD);
    gemm_mma_kernel<<<ggrid, 256, GEMM_SMEM>>>(Aexp, Wexp + 2ULL * DD * KTOT, bv, Vp, DD);

    attn_kernel<<<MTOK, 64>>>(Qp, Kp, Vp, Yp);

    convert_Aexp_kernel<<<cgrid, 256>>>(Yp, Aexp);
    gemm_mma_kernel<<<ggrid, 256, GEMM_SMEM>>>(Aexp, Wexp + 3ULL * DD * KTOT, bo, out, DD);
}